// round 5
// baseline (speedup 1.0000x reference)
#include <cuda_runtime.h>
#include <math.h>

#define B_   4
#define T_   1024
#define D_   512
#define H_   2048
#define L_   6
#define WIN  64
#define MT   (B_*T_)          // 4096 rows
#define NBTD (B_*T_*D_)       // 2,097,152

// ---------------- scratch (static __device__, alloc-free) ----------------
__device__ float g_E[NBTD];        // emb = h + pos (residual source)
__device__ float g_Q[NBTD];        // q, later y
__device__ float g_K[NBTD];        // k, later ek, later A (attn pre-LN)
__device__ float g_V[NBTD];        // v, later ek*v, later attn_out (post-LN)
__device__ float g_F1[MT*H_];      // FFN hidden
__device__ float g_ew[T_*WIN];     // banded exp weights per layer
__device__ float g_kpart[B_*8*D_]; // partial k-max
__device__ float g_kmax[B_*D_];    // k-max over T per (b,d)

// ---------------- embedding: h = tok_emb[x]*s + pos*s ----------------
__global__ void k_embed(const int* __restrict__ x, const float* __restrict__ tok,
                        const float* __restrict__ pos, float* __restrict__ h) {
    int i = blockIdx.x * blockDim.x + threadIdx.x;
    if (i >= NBTD) return;
    int d  = i % D_;
    int bt = i / D_;
    int t  = bt % T_;
    float s = rsqrtf((float)D_);
    h[i] = tok[(long)x[bt]*D_ + d] * s + pos[t*D_ + d] * s;
}

// ---------------- emb = h + pos*s ----------------
__global__ void k_addpos(const float* __restrict__ h, const float* __restrict__ pos,
                         float* __restrict__ e) {
    int i = blockIdx.x * blockDim.x + threadIdx.x;
    if (i >= NBTD) return;
    int td = i % (T_*D_);
    float s = rsqrtf((float)D_);
    e[i] = h[i] + pos[td] * s;
}

// ---------------- SGEMM: C[M,N] = A[M,K] @ B[K,N] + bias (opt ReLU) ----------------
// BM=BN=128, BK=8, 256 threads, 8x8 per thread, double-buffered smem.
template<int RELU>
__global__ __launch_bounds__(256, 2)
void k_gemm(const float* __restrict__ A, const float* __restrict__ Bm,
            const float* __restrict__ bias, float* __restrict__ C,
            int M, int N, int K) {
    __shared__ float As[2][8][128];
    __shared__ float Bs[2][8][128];

    int tid = threadIdx.x;
    int bm = blockIdx.y * 128, bn = blockIdx.x * 128;
    int arow = tid >> 1,  acol = (tid & 1) * 4;   // A tile: 128x8
    int brow = tid >> 5,  bcol = (tid & 31) * 4;  // B tile: 8x128
    int ty = tid >> 4,    tx = tid & 15;

    const float* Ap = A  + (long)(bm + arow) * K + acol;
    const float* Bp = Bm + (long)brow * N + bn + bcol;

    float4 ra = *(const float4*)(Ap);
    float4 rb = *(const float4*)(Bp);
    As[0][acol+0][arow] = ra.x; As[0][acol+1][arow] = ra.y;
    As[0][acol+2][arow] = ra.z; As[0][acol+3][arow] = ra.w;
    *(float4*)&Bs[0][brow][bcol] = rb;
    __syncthreads();

    float acc[8][8] = {};
    int nt = K >> 3;
    for (int kt = 0; kt < nt; kt++) {
        int cur = kt & 1;
        if (kt + 1 < nt) {
            ra = *(const float4*)(Ap + (kt+1)*8);
            rb = *(const float4*)(Bp + (long)(kt+1)*8*N);
        }
#pragma unroll
        for (int kk = 0; kk < 8; kk++) {
            float av[8], bv[8];
#pragma unroll
            for (int i = 0; i < 8; i++) av[i] = As[cur][kk][ty*8 + i];
#pragma unroll
            for (int j = 0; j < 8; j++) bv[j] = Bs[cur][kk][tx*8 + j];
#pragma unroll
            for (int i = 0; i < 8; i++)
#pragma unroll
                for (int j = 0; j < 8; j++)
                    acc[i][j] = fmaf(av[i], bv[j], acc[i][j]);
        }
        if (kt + 1 < nt) {
            int nb = cur ^ 1;
            As[nb][acol+0][arow] = ra.x; As[nb][acol+1][arow] = ra.y;
            As[nb][acol+2][arow] = ra.z; As[nb][acol+3][arow] = ra.w;
            *(float4*)&Bs[nb][brow][bcol] = rb;
        }
        __syncthreads();
    }

#pragma unroll
    for (int i = 0; i < 8; i++) {
        int m = bm + ty*8 + i;
#pragma unroll
        for (int j = 0; j < 8; j++) {
            int n = bn + tx*8 + j;
            float v = acc[i][j] + bias[n];
            if (RELU) v = fmaxf(v, 0.f);
            C[(long)m*N + n] = v;
        }
    }
}

// ---------------- banded exp(w_bias) with row-max stabilization ----------------
// ew[t][j] = exp(w_bias[t, t-j] - rowmax)  for j in [0, min(t,63)], else 0
__global__ void k_ew(const float* __restrict__ wb, float* __restrict__ ew) {
    int t = blockIdx.x;
    int j = threadIdx.x;              // 64 threads
    bool valid = (j <= t);
    float w = valid ? wb[(long)t*T_ + (t - j)] : -1e30f;
    __shared__ float sm[64];
    sm[j] = w; __syncthreads();
    for (int off = 32; off > 0; off >>= 1) {
        if (j < off) sm[j] = fmaxf(sm[j], sm[j+off]);
        __syncthreads();
    }
    float m = sm[0];
    ew[t*WIN + j] = valid ? expf(w - m) : 0.f;
}

// ---------------- k-max over T per (b,d): two-phase ----------------
__global__ void k_kmax_part(const float* __restrict__ K, float* __restrict__ part) {
    int b = blockIdx.y, z = blockIdx.x, d = threadIdx.x;  // 512 threads
    float m = -INFINITY;
    int t0 = z * (T_/8);
#pragma unroll 4
    for (int t = t0; t < t0 + T_/8; t++)
        m = fmaxf(m, K[((long)b*T_ + t)*D_ + d]);
    part[(b*8 + z)*D_ + d] = m;
}
__global__ void k_kmax_red(const float* __restrict__ part, float* __restrict__ kmax) {
    int b = blockIdx.x, d = threadIdx.x;
    float m = -INFINITY;
#pragma unroll
    for (int z = 0; z < 8; z++) m = fmaxf(m, part[(b*8 + z)*D_ + d]);
    kmax[b*D_ + d] = m;
}

// ---------------- ek = exp(k - kmax); ekv = ek * v (in place) ----------------
__global__ void k_ekv(float* __restrict__ K, float* __restrict__ V,
                      const float* __restrict__ kmax) {
    int i = blockIdx.x * blockDim.x + threadIdx.x;
    if (i >= NBTD) return;
    int d = i % D_;
    int b = i / (T_*D_);
    float ek = expf(K[i] - kmax[b*D_ + d]);
    K[i] = ek;
    V[i] = ek * V[i];
}

// ---------------- banded AFT: y = sigmoid(q) * num/(den+1e-9) ----------------
__global__ void k_band(const float* __restrict__ Q, const float* __restrict__ EK,
                       const float* __restrict__ EKV, const float* __restrict__ ew,
                       float* __restrict__ Y) {
    int t = blockIdx.x, b = blockIdx.y;
    int tid = threadIdx.x;            // 256 threads, 2 d-values each
    __shared__ float sw[WIN];
    if (tid < WIN) sw[tid] = ew[t*WIN + tid];
    __syncthreads();
    int jmax = min(t, WIN - 1);
    long rowt = ((long)b*T_ + t) * D_;
#pragma unroll
    for (int r = 0; r < 2; r++) {
        int d = tid + r*256;
        float num = 0.f, den = 0.f;
        for (int j = 0; j <= jmax; j++) {
            float w = sw[j];
            long rowu = ((long)b*T_ + (t - j)) * D_;
            num = fmaf(w, EKV[rowu + d], num);
            den = fmaf(w, EK [rowu + d], den);
        }
        float q = Q[rowt + d];
        float sig = 1.f / (1.f + expf(-q));
        Y[rowt + d] = sig * num / (den + 1e-9f);
    }
}

// ---------------- out = LayerNorm(X + R) * g + beta ----------------
__global__ void k_resid_ln(const float* __restrict__ X, const float* __restrict__ R,
                           const float* __restrict__ g, const float* __restrict__ bta,
                           float* __restrict__ out) {
    int row = blockIdx.x;
    int tid = threadIdx.x;            // 256 threads, D=512
    long base = (long)row * D_;
    float x0 = X[base + tid]       + R[base + tid];
    float x1 = X[base + tid + 256] + R[base + tid + 256];
    __shared__ float2 red[256];
    red[tid] = make_float2(x0 + x1, x0*x0 + x1*x1);
    __syncthreads();
    for (int off = 128; off > 0; off >>= 1) {
        if (tid < off) {
            red[tid].x += red[tid+off].x;
            red[tid].y += red[tid+off].y;
        }
        __syncthreads();
    }
    float mean = red[0].x * (1.f/D_);
    float var  = red[0].y * (1.f/D_) - mean*mean;
    float rs = rsqrtf(var + 1e-5f);
    out[base + tid]       = (x0 - mean)*rs*g[tid]       + bta[tid];
    out[base + tid + 256] = (x1 - mean)*rs*g[tid + 256] + bta[tid + 256];
}

// ---------------- orchestration ----------------
extern "C" void kernel_launch(void* const* d_in, const int* in_sizes, int n_in,
                              void* d_out, int out_size) {
    const int*   x     = (const int*)  d_in[0];
    const float* tok   = (const float*)d_in[1];
    const float* pos   = (const float*)d_in[2];
    const float* Wq    = (const float*)d_in[3];
    const float* bq    = (const float*)d_in[4];
    const float* Wk    = (const float*)d_in[5];
    const float* bk    = (const float*)d_in[6];
    const float* Wv    = (const float*)d_in[7];
    const float* bv    = (const float*)d_in[8];
    const float* Wo    = (const float*)d_in[9];
    const float* bo    = (const float*)d_in[10];
    const float* wbias = (const float*)d_in[11];
    const float* lng   = (const float*)d_in[12];
    const float* lnb   = (const float*)d_in[13];
    const float* W1    = (const float*)d_in[14];
    const float* b1    = (const float*)d_in[15];
    const float* W2    = (const float*)d_in[16];
    const float* b2    = (const float*)d_in[17];
    float* H = (float*)d_out;   // residual stream lives in d_out

    float *E, *Q, *K, *V, *F1, *EW, *KP, *KM;
    cudaGetSymbolAddress((void**)&E,  g_E);
    cudaGetSymbolAddress((void**)&Q,  g_Q);
    cudaGetSymbolAddress((void**)&K,  g_K);
    cudaGetSymbolAddress((void**)&V,  g_V);
    cudaGetSymbolAddress((void**)&F1, g_F1);
    cudaGetSymbolAddress((void**)&EW, g_ew);
    cudaGetSymbolAddress((void**)&KP, g_kpart);
    cudaGetSymbolAddress((void**)&KM, g_kmax);

    const int EL_BLK = 256;
    const int EL_GRID = (NBTD + EL_BLK - 1) / EL_BLK;
    dim3 g512(D_/128, MT/128);    // (4, 32)
    dim3 gH  (H_/128, MT/128);    // (16, 32)

    k_embed<<<EL_GRID, EL_BLK>>>(x, tok, pos, H);

    for (int i = 0; i < L_; i++) {
        const float* Wqi = Wq + (long)i*D_*D_;  const float* bqi = bq + i*D_;
        const float* Wki = Wk + (long)i*D_*D_;  const float* bki = bk + i*D_;
        const float* Wvi = Wv + (long)i*D_*D_;  const float* bvi = bv + i*D_;
        const float* Woi = Wo + (long)i*D_*D_;  const float* boi = bo + i*D_;
        const float* W1i = W1 + (long)i*D_*H_;  const float* b1i = b1 + i*H_;
        const float* W2i = W2 + (long)i*H_*D_;  const float* b2i = b2 + i*D_;
        const float* wbi = wbias + (long)i*T_*T_;
        const float* gi  = lng + i*D_;
        const float* bi  = lnb + i*D_;

        // emb = h + pos*s
        k_addpos<<<EL_GRID, EL_BLK>>>(H, pos, E);

        // q,k,v projections
        k_gemm<0><<<g512, 256>>>(E, Wqi, bqi, Q, MT, D_, D_);
        k_gemm<0><<<g512, 256>>>(E, Wki, bki, K, MT, D_, D_);
        k_gemm<0><<<g512, 256>>>(E, Wvi, bvi, V, MT, D_, D_);

        // banded position weights
        k_ew<<<T_, WIN>>>(wbi, EW);

        // key max over T, then ek / ek*v in place
        k_kmax_part<<<dim3(8, B_), D_>>>(K, KP);
        k_kmax_red<<<B_, D_>>>(KP, KM);
        k_ekv<<<EL_GRID, EL_BLK>>>(K, V, KM);

        // banded aggregation + gate -> Y (in place over Q)
        k_band<<<dim3(T_, B_), 256>>>(Q, K, V, EW, Q);

        // output projection -> A (reuse K)
        k_gemm<0><<<g512, 256>>>(Q, Woi, boi, K, MT, D_, D_);

        // attn_out = LN(A + emb) -> reuse V
        k_resid_ln<<<MT, 256>>>(K, E, gi, bi, V);

        // FFN
        k_gemm<1><<<gH,   256>>>(V,  W1i, b1i, F1, MT, H_, D_);
        k_gemm<0><<<g512, 256>>>(F1, W2i, b2i, E,  MT, D_, H_);   // F2 -> reuse E

        // h = LN(F2 + attn_out) -> residual stream (d_out)
        k_resid_ln<<<MT, 256>>>(E, V, gi, bi, H);
    }
}

// round 6
// speedup vs baseline: 1.0074x; 1.0074x over previous
#include <cuda_runtime.h>
#include <math.h>

#define B_   4
#define T_   1024
#define D_   512
#define H_   2048
#define L_   6
#define WIN  64
#define MT   (B_*T_)          // 4096 rows
#define NBTD (B_*T_*D_)       // 2,097,152

// ---------------- scratch (static __device__, alloc-free) ----------------
__device__ float g_E[NBTD];        // emb = h + pos (residual source)
__device__ float g_Q[NBTD];        // q, later y
__device__ float g_K[NBTD];        // k, later ek, later A (attn pre-LN)
__device__ float g_V[NBTD];        // v, later ek*v, later attn_out (post-LN)
__device__ float g_F1[MT*H_];      // FFN hidden
__device__ float g_ew[T_*WIN];     // banded exp weights per layer
__device__ float g_kpart[B_*8*D_]; // partial k-max
__device__ float g_kmax[B_*D_];    // k-max over T per (b,d)

// ---------------- embedding: h = tok_emb[x]*s + pos*s ----------------
__global__ void k_embed(const int* __restrict__ x, const float* __restrict__ tok,
                        const float* __restrict__ pos, float* __restrict__ h) {
    int i = blockIdx.x * blockDim.x + threadIdx.x;
    if (i >= NBTD) return;
    int d  = i % D_;
    int bt = i / D_;
    int t  = bt % T_;
    float s = rsqrtf((float)D_);
    h[i] = tok[(long)x[bt]*D_ + d] * s + pos[t*D_ + d] * s;
}

// ---------------- emb = h + pos*s ----------------
__global__ void k_addpos(const float* __restrict__ h, const float* __restrict__ pos,
                         float* __restrict__ e) {
    int i = blockIdx.x * blockDim.x + threadIdx.x;
    if (i >= NBTD) return;
    int td = i % (T_*D_);
    float s = rsqrtf((float)D_);
    e[i] = h[i] + pos[td] * s;
}

// ---------------- SGEMM: C[M,N] = A[M,K] @ B[K,N] + bias (opt ReLU) ----------------
// BM=BN=128, BK=8, 256 threads, 8x8 per thread, double-buffered smem.
template<int RELU>
__global__ __launch_bounds__(256, 2)
void k_gemm(const float* __restrict__ A, const float* __restrict__ Bm,
            const float* __restrict__ bias, float* __restrict__ C,
            int M, int N, int K) {
    __shared__ float As[2][8][128];
    __shared__ float Bs[2][8][128];

    int tid = threadIdx.x;
    int bm = blockIdx.y * 128, bn = blockIdx.x * 128;
    int arow = tid >> 1,  acol = (tid & 1) * 4;   // A tile: 128x8
    int brow = tid >> 5,  bcol = (tid & 31) * 4;  // B tile: 8x128
    int ty = tid >> 4,    tx = tid & 15;

    const float* Ap = A  + (long)(bm + arow) * K + acol;
    const float* Bp = Bm + (long)brow * N + bn + bcol;

    float4 ra = *(const float4*)(Ap);
    float4 rb = *(const float4*)(Bp);
    As[0][acol+0][arow] = ra.x; As[0][acol+1][arow] = ra.y;
    As[0][acol+2][arow] = ra.z; As[0][acol+3][arow] = ra.w;
    *(float4*)&Bs[0][brow][bcol] = rb;
    __syncthreads();

    float acc[8][8] = {};
    int nt = K >> 3;
    for (int kt = 0; kt < nt; kt++) {
        int cur = kt & 1;
        if (kt + 1 < nt) {
            ra = *(const float4*)(Ap + (kt+1)*8);
            rb = *(const float4*)(Bp + (long)(kt+1)*8*N);
        }
#pragma unroll
        for (int kk = 0; kk < 8; kk++) {
            float av[8], bv[8];
#pragma unroll
            for (int i = 0; i < 8; i++) av[i] = As[cur][kk][ty*8 + i];
#pragma unroll
            for (int j = 0; j < 8; j++) bv[j] = Bs[cur][kk][tx*8 + j];
#pragma unroll
            for (int i = 0; i < 8; i++)
#pragma unroll
                for (int j = 0; j < 8; j++)
                    acc[i][j] = fmaf(av[i], bv[j], acc[i][j]);
        }
        if (kt + 1 < nt) {
            int nb = cur ^ 1;
            As[nb][acol+0][arow] = ra.x; As[nb][acol+1][arow] = ra.y;
            As[nb][acol+2][arow] = ra.z; As[nb][acol+3][arow] = ra.w;
            *(float4*)&Bs[nb][brow][bcol] = rb;
        }
        __syncthreads();
    }

#pragma unroll
    for (int i = 0; i < 8; i++) {
        int m = bm + ty*8 + i;
#pragma unroll
        for (int j = 0; j < 8; j++) {
            int n = bn + tx*8 + j;
            float v = acc[i][j] + bias[n];
            if (RELU) v = fmaxf(v, 0.f);
            C[(long)m*N + n] = v;
        }
    }
}

// ---------------- banded exp(w_bias) with row-max stabilization ----------------
// ew[t][j] = exp(w_bias[t, t-j] - rowmax)  for j in [0, min(t,63)], else 0
__global__ void k_ew(const float* __restrict__ wb, float* __restrict__ ew) {
    int t = blockIdx.x;
    int j = threadIdx.x;              // 64 threads
    bool valid = (j <= t);
    float w = valid ? wb[(long)t*T_ + (t - j)] : -1e30f;
    __shared__ float sm[64];
    sm[j] = w; __syncthreads();
    for (int off = 32; off > 0; off >>= 1) {
        if (j < off) sm[j] = fmaxf(sm[j], sm[j+off]);
        __syncthreads();
    }
    float m = sm[0];
    ew[t*WIN + j] = valid ? expf(w - m) : 0.f;
}

// ---------------- k-max over T per (b,d): two-phase ----------------
__global__ void k_kmax_part(const float* __restrict__ K, float* __restrict__ part) {
    int b = blockIdx.y, z = blockIdx.x, d = threadIdx.x;  // 512 threads
    float m = -INFINITY;
    int t0 = z * (T_/8);
#pragma unroll 4
    for (int t = t0; t < t0 + T_/8; t++)
        m = fmaxf(m, K[((long)b*T_ + t)*D_ + d]);
    part[(b*8 + z)*D_ + d] = m;
}
__global__ void k_kmax_red(const float* __restrict__ part, float* __restrict__ kmax) {
    int b = blockIdx.x, d = threadIdx.x;
    float m = -INFINITY;
#pragma unroll
    for (int z = 0; z < 8; z++) m = fmaxf(m, part[(b*8 + z)*D_ + d]);
    kmax[b*D_ + d] = m;
}

// ---------------- ek = exp(k - kmax); ekv = ek * v (in place) ----------------
__global__ void k_ekv(float* __restrict__ K, float* __restrict__ V,
                      const float* __restrict__ kmax) {
    int i = blockIdx.x * blockDim.x + threadIdx.x;
    if (i >= NBTD) return;
    int d = i % D_;
    int b = i / (T_*D_);
    float ek = expf(K[i] - kmax[b*D_ + d]);
    K[i] = ek;
    V[i] = ek * V[i];
}

// ---------------- banded AFT: y = sigmoid(q) * num/(den+1e-9) ----------------
__global__ void k_band(const float* __restrict__ Q, const float* __restrict__ EK,
                       const float* __restrict__ EKV, const float* __restrict__ ew,
                       float* __restrict__ Y) {
    int t = blockIdx.x, b = blockIdx.y;
    int tid = threadIdx.x;            // 256 threads, 2 d-values each
    __shared__ float sw[WIN];
    if (tid < WIN) sw[tid] = ew[t*WIN + tid];
    __syncthreads();
    int jmax = min(t, WIN - 1);
    long rowt = ((long)b*T_ + t) * D_;
#pragma unroll
    for (int r = 0; r < 2; r++) {
        int d = tid + r*256;
        float num = 0.f, den = 0.f;
        for (int j = 0; j <= jmax; j++) {
            float w = sw[j];
            long rowu = ((long)b*T_ + (t - j)) * D_;
            num = fmaf(w, EKV[rowu + d], num);
            den = fmaf(w, EK [rowu + d], den);
        }
        float q = Q[rowt + d];
        float sig = 1.f / (1.f + expf(-q));
        Y[rowt + d] = sig * num / (den + 1e-9f);
    }
}

// ---------------- out = LayerNorm(X + R) * g + beta ----------------
__global__ void k_resid_ln(const float* __restrict__ X, const float* __restrict__ R,
                           const float* __restrict__ g, const float* __restrict__ bta,
                           float* __restrict__ out) {
    int row = blockIdx.x;
    int tid = threadIdx.x;            // 256 threads, D=512
    long base = (long)row * D_;
    float x0 = X[base + tid]       + R[base + tid];
    float x1 = X[base + tid + 256] + R[base + tid + 256];
    __shared__ float2 red[256];
    red[tid] = make_float2(x0 + x1, x0*x0 + x1*x1);
    __syncthreads();
    for (int off = 128; off > 0; off >>= 1) {
        if (tid < off) {
            red[tid].x += red[tid+off].x;
            red[tid].y += red[tid+off].y;
        }
        __syncthreads();
    }
    float mean = red[0].x * (1.f/D_);
    float var  = red[0].y * (1.f/D_) - mean*mean;
    float rs = rsqrtf(var + 1e-5f);
    out[base + tid]       = (x0 - mean)*rs*g[tid]       + bta[tid];
    out[base + tid + 256] = (x1 - mean)*rs*g[tid + 256] + bta[tid + 256];
}

// ---------------- orchestration ----------------
extern "C" void kernel_launch(void* const* d_in, const int* in_sizes, int n_in,
                              void* d_out, int out_size) {
    const int*   x     = (const int*)  d_in[0];
    const float* tok   = (const float*)d_in[1];
    const float* pos   = (const float*)d_in[2];
    const float* Wq    = (const float*)d_in[3];
    const float* bq    = (const float*)d_in[4];
    const float* Wk    = (const float*)d_in[5];
    const float* bk    = (const float*)d_in[6];
    const float* Wv    = (const float*)d_in[7];
    const float* bv    = (const float*)d_in[8];
    const float* Wo    = (const float*)d_in[9];
    const float* bo    = (const float*)d_in[10];
    const float* wbias = (const float*)d_in[11];
    const float* lng   = (const float*)d_in[12];
    const float* lnb   = (const float*)d_in[13];
    const float* W1    = (const float*)d_in[14];
    const float* b1    = (const float*)d_in[15];
    const float* W2    = (const float*)d_in[16];
    const float* b2    = (const float*)d_in[17];
    float* H = (float*)d_out;   // residual stream lives in d_out

    float *E, *Q, *K, *V, *F1, *EW, *KP, *KM;
    cudaGetSymbolAddress((void**)&E,  g_E);
    cudaGetSymbolAddress((void**)&Q,  g_Q);
    cudaGetSymbolAddress((void**)&K,  g_K);
    cudaGetSymbolAddress((void**)&V,  g_V);
    cudaGetSymbolAddress((void**)&F1, g_F1);
    cudaGetSymbolAddress((void**)&EW, g_ew);
    cudaGetSymbolAddress((void**)&KP, g_kpart);
    cudaGetSymbolAddress((void**)&KM, g_kmax);

    const int EL_BLK = 256;
    const int EL_GRID = (NBTD + EL_BLK - 1) / EL_BLK;
    dim3 g512(D_/128, MT/128);    // (4, 32)
    dim3 gH  (H_/128, MT/128);    // (16, 32)

    k_embed<<<EL_GRID, EL_BLK>>>(x, tok, pos, H);

    for (int i = 0; i < L_; i++) {
        const float* Wqi = Wq + (long)i*D_*D_;  const float* bqi = bq + i*D_;
        const float* Wki = Wk + (long)i*D_*D_;  const float* bki = bk + i*D_;
        const float* Wvi = Wv + (long)i*D_*D_;  const float* bvi = bv + i*D_;
        const float* Woi = Wo + (long)i*D_*D_;  const float* boi = bo + i*D_;
        const float* W1i = W1 + (long)i*D_*H_;  const float* b1i = b1 + i*H_;
        const float* W2i = W2 + (long)i*H_*D_;  const float* b2i = b2 + i*D_;
        const float* wbi = wbias + (long)i*T_*T_;
        const float* gi  = lng + i*D_;
        const float* bi  = lnb + i*D_;

        // emb = h + pos*s
        k_addpos<<<EL_GRID, EL_BLK>>>(H, pos, E);

        // q,k,v projections
        k_gemm<0><<<g512, 256>>>(E, Wqi, bqi, Q, MT, D_, D_);
        k_gemm<0><<<g512, 256>>>(E, Wki, bki, K, MT, D_, D_);
        k_gemm<0><<<g512, 256>>>(E, Wvi, bvi, V, MT, D_, D_);

        // banded position weights
        k_ew<<<T_, WIN>>>(wbi, EW);

        // key max over T, then ek / ek*v in place
        k_kmax_part<<<dim3(8, B_), D_>>>(K, KP);
        k_kmax_red<<<B_, D_>>>(KP, KM);
        k_ekv<<<EL_GRID, EL_BLK>>>(K, V, KM);

        // banded aggregation + gate -> Y (in place over Q)
        k_band<<<dim3(T_, B_), 256>>>(Q, K, V, EW, Q);

        // output projection -> A (reuse K)
        k_gemm<0><<<g512, 256>>>(Q, Woi, boi, K, MT, D_, D_);

        // attn_out = LN(A + emb) -> reuse V
        k_resid_ln<<<MT, 256>>>(K, E, gi, bi, V);

        // FFN
        k_gemm<1><<<gH,   256>>>(V,  W1i, b1i, F1, MT, H_, D_);
        k_gemm<0><<<g512, 256>>>(F1, W2i, b2i, E,  MT, D_, H_);   // F2 -> reuse E

        // h = LN(F2 + attn_out) -> residual stream (d_out)
        k_resid_ln<<<MT, 256>>>(E, V, gi, bi, H);
    }
}